// round 2
// baseline (speedup 1.0000x reference)
#include <cuda_runtime.h>
#include <cstdint>
#include <math.h>

// Problem constants (fixed by the dataset)
#define SN       150000      // s_n
#define DIM      512         // d
#define NB       100         // N_USE
#define NPAD     128         // padded n (multiple of 8 for MMA)
#define TALF     0.07f
#define S_PER_CTA 256
#define NCTA     ((SN + S_PER_CTA - 1) / S_PER_CTA)   // 586

// Scratch (static __device__ — no allocations allowed)
__device__ __align__(16) float g_B[64 * 128 * 8];  // prescaled, fragment-permuted features
__device__ float g_Psum[NCTA * NPAD];              // per-CTA partial sum of exp
__device__ float g_pos[NPAD];                      // ex[label[n], n]

// ---------------------------------------------------------------------------
// tf32 m16n8k8 warp MMA (row.col). A: 4 regs, B: 2 regs, C/D: 4 fp32.
// ---------------------------------------------------------------------------
__device__ __forceinline__ void mma_tf32(float c[4], const unsigned a[4],
                                         unsigned b0, unsigned b1) {
    asm volatile(
        "mma.sync.aligned.m16n8k8.row.col.f32.tf32.tf32.f32 "
        "{%0,%1,%2,%3},{%4,%5,%6,%7},{%8,%9},{%0,%1,%2,%3};\n"
        : "+f"(c[0]), "+f"(c[1]), "+f"(c[2]), "+f"(c[3])
        : "r"(a[0]), "r"(a[1]), "r"(a[2]), "r"(a[3]), "r"(b0), "r"(b1));
}

__device__ __forceinline__ void cp_async16(void* smem_dst, const void* gsrc) {
    unsigned s = (unsigned)__cvta_generic_to_shared(smem_dst);
    asm volatile("cp.async.cg.shared.global [%0], [%1], 16;\n" :: "r"(s), "l"(gsrc));
}

// ---------------------------------------------------------------------------
// prep: B'[n,k] = fea[n,k] / (TAL * ||fea[n]||), zero-padded to 128 rows,
// stored permuted so the warp B-fragment (b0: k=tig, b1: k=tig+4) is one LDS.64.
// Layout: g_B[(kstep*128 + n)*8 + c], kstep = k/8, c = (k&3)*2 + ((k>>2)&1).
// ---------------------------------------------------------------------------
__global__ void prep_kernel(const float* __restrict__ fea) {
    int n = blockIdx.x;      // 0..127
    int t = threadIdx.x;     // 128 threads
    __shared__ float red[128];
    float v[4];
    float ss = 0.0f;
    if (n < NB) {
#pragma unroll
        for (int i = 0; i < 4; i++) {
            v[i] = fea[n * DIM + t + i * 128];
            ss += v[i] * v[i];
        }
    } else {
        v[0] = v[1] = v[2] = v[3] = 0.0f;
    }
    red[t] = ss;
    __syncthreads();
    for (int off = 64; off > 0; off >>= 1) {
        if (t < off) red[t] += red[t + off];
        __syncthreads();
    }
    float scale = (n < NB) ? (rsqrtf(red[0]) / TALF) : 0.0f;
#pragma unroll
    for (int i = 0; i < 4; i++) {
        int k = t + i * 128;
        int kin = k & 7;
        int c = ((kin & 3) << 1) | ((kin >> 2) & 1);
        int kstep = k >> 3;
        g_B[(kstep * 128 + n) * 8 + c] = v[i] * scale;
    }
}

// ---------------------------------------------------------------------------
// pos: ex[label[n], n] recomputed exactly (fp32). 100 blocks, 128 threads.
// Label buffer may be int32 or int64 (JAX x64 flag dependent) — sniff it:
// if it is int64, every high word (odd 32-bit word) of the first entries is 0.
// ---------------------------------------------------------------------------
__global__ void pos_kernel(const float* __restrict__ att,
                           const float* __restrict__ fea,
                           const int* __restrict__ label_raw) {
    int n = blockIdx.x;      // 0..NB-1
    int t = threadIdx.x;     // 128

    bool is64 = (label_raw[1] == 0) && (label_raw[3] == 0) &&
                (label_raw[5] == 0) && (label_raw[7] == 0);
    int lab = is64 ? (int)(((const long long*)label_raw)[n]) : label_raw[n];
    if (lab < 0) lab = 0;
    if (lab >= SN) lab = SN - 1;   // defensive: wrong guess -> rel_err, not crash

    float dot = 0.f, asq = 0.f, fsq = 0.f;
    for (int d = t; d < DIM; d += 128) {
        float a = att[(size_t)d * SN + (size_t)lab];
        float f = fea[n * DIM + d];
        dot += a * f;
        asq += a * a;
        fsq += f * f;
    }
    __shared__ float r1[128], r2[128], r3[128];
    r1[t] = dot; r2[t] = asq; r3[t] = fsq;
    __syncthreads();
    for (int off = 64; off > 0; off >>= 1) {
        if (t < off) { r1[t] += r1[t + off]; r2[t] += r2[t + off]; r3[t] += r3[t + off]; }
        __syncthreads();
    }
    if (t == 0)
        g_pos[n] = r1[0] / (TALF * sqrtf(r2[0]) * sqrtf(r3[0]));
}

// ---------------------------------------------------------------------------
// main: each CTA = 256 s-rows x 128 n-cols, 16 warps.
//   warp w: s-group = w/2 (32 rows), n-half = w%2 (64 cols)
//   A fragments loaded straight from gmem (coalesced 128B/inst), B from smem
//   (double-buffered cp.async, conflict-free LDS.64 fragments).
//   Accumulates ||att[:,s]||^2 from the same A fragments for free.
//   Epilogue: ex = acc * rsqrt(norm2), colsum += expf(ex), deterministic
//   in-block reduction, one partial row per CTA to g_Psum.
// ---------------------------------------------------------------------------
__global__ void __launch_bounds__(512, 1)
main_kernel(const float* __restrict__ att) {
    __shared__ __align__(16) float Bs[2][4 * 128 * 8];   // 2 x 16 KB
    __shared__ float snorm[S_PER_CTA];
    __shared__ float colacc[8][NPAD];

    const int tid   = threadIdx.x;
    const int lane  = tid & 31;
    const int warp  = tid >> 5;
    const int gid   = lane >> 2;   // 0..7
    const int tig   = lane & 3;    // 0..3
    const int sgrp  = warp >> 1;   // 0..7
    const int nhalf = warp & 1;    // 0..1
    const int s_w   = blockIdx.x * S_PER_CTA + sgrp * 32;
    const int n_w   = nhalf * 64;

    int  srow[4];
    bool pv[4];
#pragma unroll
    for (int j = 0; j < 4; j++) {
        srow[j] = s_w + 8 * j + gid;
        pv[j]   = (srow[j] < SN);
    }

    float acc[2][8][4];
#pragma unroll
    for (int a = 0; a < 2; a++)
#pragma unroll
        for (int b = 0; b < 8; b++)
#pragma unroll
            for (int c = 0; c < 4; c++) acc[a][b][c] = 0.0f;
    float sq[4] = {0.f, 0.f, 0.f, 0.f};

    const float* attk = att + (size_t)tig * SN;

    // prologue: stage K-chunk 0
    {
        const float* src = g_B;
        float* dst = &Bs[0][0];
#pragma unroll
        for (int i = 0; i < 2; i++) {
            int f = (tid + i * 512) * 4;
            cp_async16(dst + f, src + f);
        }
        asm volatile("cp.async.commit_group;\n");
    }

    for (int kt = 0; kt < 16; ++kt) {
        if (kt < 15) {
            const float* src = g_B + (kt + 1) * 4096;
            float* dst = &Bs[(kt + 1) & 1][0];
#pragma unroll
            for (int i = 0; i < 2; i++) {
                int f = (tid + i * 512) * 4;
                cp_async16(dst + f, src + f);
            }
            asm volatile("cp.async.commit_group;\n");
            asm volatile("cp.async.wait_group 1;\n");
        } else {
            asm volatile("cp.async.wait_group 0;\n");
        }
        __syncthreads();

        const float* bsbase = &Bs[kt & 1][0];
#pragma unroll
        for (int ks = 0; ks < 4; ++ks) {
            unsigned A[2][4];
#pragma unroll
            for (int mf = 0; mf < 2; ++mf) {
                int j0 = 2 * mf, j1 = 2 * mf + 1;
                float a0 = pv[j0] ? attk[srow[j0]] : 0.0f;
                float a1 = pv[j1] ? attk[srow[j1]] : 0.0f;
                float a2 = pv[j0] ? attk[(size_t)4 * SN + srow[j0]] : 0.0f;
                float a3 = pv[j1] ? attk[(size_t)4 * SN + srow[j1]] : 0.0f;
                sq[j0] += a0 * a0 + a2 * a2;
                sq[j1] += a1 * a1 + a3 * a3;
                A[mf][0] = __float_as_uint(a0);
                A[mf][1] = __float_as_uint(a1);
                A[mf][2] = __float_as_uint(a2);
                A[mf][3] = __float_as_uint(a3);
            }
            attk += (size_t)8 * SN;
            const float* brow = bsbase + ks * 1024 + tig * 2;
#pragma unroll
            for (int nt = 0; nt < 8; ++nt) {
                int n = n_w + nt * 8 + gid;
                float2 b = *(const float2*)(brow + n * 8);
                unsigned b0 = __float_as_uint(b.x);
                unsigned b1 = __float_as_uint(b.y);
                mma_tf32(acc[0][nt], A[0], b0, b1);
                mma_tf32(acc[1][nt], A[1], b0, b1);
            }
        }
        __syncthreads();
    }

    // reduce norm^2 across the 4 lanes of each quad (tig dimension)
#pragma unroll
    for (int j = 0; j < 4; j++) {
        sq[j] += __shfl_xor_sync(0xffffffffu, sq[j], 1);
        sq[j] += __shfl_xor_sync(0xffffffffu, sq[j], 2);
    }
    if (nhalf == 0 && tig == 0) {
#pragma unroll
        for (int j = 0; j < 4; j++)
            snorm[sgrp * 32 + 8 * j + gid] = sq[j];
    }
    __syncthreads();

    float inv[4];
#pragma unroll
    for (int j = 0; j < 4; j++)
        inv[j] = rsqrtf(snorm[sgrp * 32 + 8 * j + gid]);

    // epilogue: ex = acc * inv_att_norm (fea norm & TAL pre-folded), sum exp
#pragma unroll
    for (int nt = 0; nt < 8; ++nt) {
        float s0 = 0.f, s1 = 0.f;
#pragma unroll
        for (int mf = 0; mf < 2; ++mf) {
            int j0 = 2 * mf, j1 = 2 * mf + 1;
            if (pv[j0]) {
                s0 += __expf(acc[mf][nt][0] * inv[j0]);
                s1 += __expf(acc[mf][nt][1] * inv[j0]);
            }
            if (pv[j1]) {
                s0 += __expf(acc[mf][nt][2] * inv[j1]);
                s1 += __expf(acc[mf][nt][3] * inv[j1]);
            }
        }
        // reduce across gid (lanes differing by 4, 8, 16)
        s0 += __shfl_down_sync(0xffffffffu, s0, 16);
        s1 += __shfl_down_sync(0xffffffffu, s1, 16);
        s0 += __shfl_down_sync(0xffffffffu, s0, 8);
        s1 += __shfl_down_sync(0xffffffffu, s1, 8);
        s0 += __shfl_down_sync(0xffffffffu, s0, 4);
        s1 += __shfl_down_sync(0xffffffffu, s1, 4);
        if (gid == 0) {
            colacc[sgrp][n_w + nt * 8 + 2 * tig]     = s0;
            colacc[sgrp][n_w + nt * 8 + 2 * tig + 1] = s1;
        }
    }
    __syncthreads();

    if (tid < NPAD) {
        float t = 0.f;
#pragma unroll
        for (int g = 0; g < 8; ++g) t += colacc[g][tid];
        g_Psum[blockIdx.x * NPAD + tid] = t;
    }
}

// ---------------------------------------------------------------------------
// final: loss = (1/NB) * sum_n ( log(sum_s exp(ex)) - ex[label[n], n] )
// ---------------------------------------------------------------------------
__global__ void final_kernel(float* __restrict__ out) {
    int t = threadIdx.x;   // 128
    __shared__ float red[128];
    float v = 0.0f;
    if (t < NB) {
        float s = 0.0f;
        for (int c = 0; c < NCTA; c++) s += g_Psum[c * NPAD + t];
        v = logf(s) - g_pos[t];
    }
    red[t] = v;
    __syncthreads();
    for (int off = 64; off > 0; off >>= 1) {
        if (t < off) red[t] += red[t + off];
        __syncthreads();
    }
    if (t == 0) out[0] = red[0] / (float)NB;
}

// ---------------------------------------------------------------------------
extern "C" void kernel_launch(void* const* d_in, const int* in_sizes, int n_in,
                              void* d_out, int out_size) {
    // Resolve inputs by element count (robust to metadata ordering):
    //   attribute_vec: 512*150000 = 76,800,000 floats
    //   feature:       4096*512   =  2,097,152 floats
    //   label:         4096 elements (int32 or int64 — sniffed on device)
    int ia = 0, ifea = 1, ilab = 2;
    for (int i = 0; i < n_in; i++) {
        if (in_sizes[i] > 10000000) ia = i;
        else if (in_sizes[i] > 100000) ifea = i;
        else ilab = i;
    }
    const float* att   = (const float*)d_in[ia];
    const float* fea   = (const float*)d_in[ifea];
    const int*   label = (const int*)d_in[ilab];
    float* out = (float*)d_out;

    prep_kernel<<<NPAD, 128>>>(fea);
    pos_kernel<<<NB, 128>>>(att, fea, label);
    main_kernel<<<NCTA, 512>>>(att);
    final_kernel<<<1, 128>>>(out);
}

// round 4
// speedup vs baseline: 1.0613x; 1.0613x over previous
#include <cuda_runtime.h>
#include <cuda_bf16.h>
#include <cstdint>
#include <math.h>

#define SN       150000
#define DIM      512
#define NB       100
#define TALF     0.07f
#define S_PER_CTA 256
#define NCTA     ((SN + S_PER_CTA - 1) / S_PER_CTA)   // 586

// Static device scratch (no allocations allowed)
// g_B: bf16x2 words, fragment-packed:  word[(kstep*128 + n)*8 + c]
//   kstep = k/16 (32 steps), c encodes the k-pair within the 16-k step:
//   for even r = k%16:  c = (r<8) ? r : r-7   (so c=2*tig -> b0 pair, c=2*tig+1 -> b1 pair)
__device__ __align__(1024) unsigned g_B[32 * 128 * 8];   // 128 KB
__device__ float g_Psum[NCTA * 128];
__device__ float g_pos[128];
__device__ float g_logZ[128];

// ---------------------------------------------------------------------------
__device__ __forceinline__ unsigned pack_bf16x2(float lo, float hi) {
    unsigned r;  // first source -> high half
    asm("cvt.rn.bf16x2.f32 %0, %1, %2;" : "=r"(r) : "f"(hi), "f"(lo));
    return r;
}
__device__ __forceinline__ void mma_bf16(float c[4], const unsigned a[4],
                                         unsigned b0, unsigned b1) {
    asm volatile(
        "mma.sync.aligned.m16n8k16.row.col.f32.bf16.bf16.f32 "
        "{%0,%1,%2,%3},{%4,%5,%6,%7},{%8,%9},{%0,%1,%2,%3};\n"
        : "+f"(c[0]), "+f"(c[1]), "+f"(c[2]), "+f"(c[3])
        : "r"(a[0]), "r"(a[1]), "r"(a[2]), "r"(a[3]), "r"(b0), "r"(b1));
}
__device__ __forceinline__ void cp_async16(void* smem_dst, const void* gsrc) {
    unsigned s = (unsigned)__cvta_generic_to_shared(smem_dst);
    asm volatile("cp.async.cg.shared.global [%0], [%1], 16;\n" :: "r"(s), "l"(gsrc));
}

// ---------------------------------------------------------------------------
// prep: B'[n][k] = bf16( fea[n][k] / (TAL*||fea[n]||) ), n zero-padded to 128,
// packed into g_B fragment layout. One block per n (128 blocks, 128 threads).
// ---------------------------------------------------------------------------
__global__ void prep_kernel(const float* __restrict__ fea) {
    int n = blockIdx.x;   // 0..127
    int t = threadIdx.x;  // 128
    __shared__ float red[128];
    __shared__ float row[512];
    float v[4]; float ss = 0.f;
    if (n < NB) {
#pragma unroll
        for (int i = 0; i < 4; i++) { v[i] = fea[n * DIM + t + i * 128]; ss += v[i] * v[i]; }
    } else { v[0] = v[1] = v[2] = v[3] = 0.f; }
    red[t] = ss; __syncthreads();
    for (int off = 64; off > 0; off >>= 1) { if (t < off) red[t] += red[t + off]; __syncthreads(); }
    float scale = (n < NB) ? (rsqrtf(red[0]) / TALF) : 0.f;
#pragma unroll
    for (int i = 0; i < 4; i++) row[t + i * 128] = v[i] * scale;
    __syncthreads();
    // each thread packs 2 k-pairs: k0 = 4t and 4t+2
#pragma unroll
    for (int i = 0; i < 2; i++) {
        int k0 = 4 * t + 2 * i;           // even, 0..510
        int kstep = k0 >> 4;
        int r = k0 & 15;
        int c = (r < 8) ? r : (r - 7);
        g_B[(kstep * 128 + n) * 8 + c] = pack_bf16x2(row[k0], row[k0 + 1]);
    }
}

// ---------------------------------------------------------------------------
// pos: ex[label[n], n] exact fp32; label dtype sniffed (int64 vs int32)
// ---------------------------------------------------------------------------
__global__ void pos_kernel(const float* __restrict__ att,
                           const float* __restrict__ fea,
                           const int* __restrict__ label_raw) {
    int n = blockIdx.x, t = threadIdx.x;
    bool is64 = (label_raw[1] == 0) && (label_raw[3] == 0) &&
                (label_raw[5] == 0) && (label_raw[7] == 0);
    int lab = is64 ? (int)(((const long long*)label_raw)[n]) : label_raw[n];
    if (lab < 0) lab = 0;
    if (lab >= SN) lab = SN - 1;
    float dot = 0.f, asq = 0.f, fsq = 0.f;
    for (int d = t; d < DIM; d += 128) {
        float a = att[(size_t)d * SN + (size_t)lab];
        float f = fea[n * DIM + d];
        dot += a * f; asq += a * a; fsq += f * f;
    }
    __shared__ float r1[128], r2[128], r3[128];
    r1[t] = dot; r2[t] = asq; r3[t] = fsq; __syncthreads();
    for (int off = 64; off > 0; off >>= 1) {
        if (t < off) { r1[t] += r1[t+off]; r2[t] += r2[t+off]; r3[t] += r3[t+off]; }
        __syncthreads();
    }
    if (t == 0) g_pos[n] = r1[0] / (TALF * sqrtf(r2[0]) * sqrtf(r3[0]));
}

// ---------------------------------------------------------------------------
// main: 586 CTAs x 512 threads (16 warps). CTA tile 256 s x 128 n, K=512.
//   warp: sgrp = warp/2 (32 s-rows), nhalf = warp%2 (64 n-cols).
//   bf16 m16n8k16; A gmem->fp32 regs (exact norms) -> bf16x2; B from smem,
//   double-buffered cp.async chunks (64 k = 16 KB bf16 each).
// ---------------------------------------------------------------------------
__global__ void __launch_bounds__(512, 1)
main_kernel(const float* __restrict__ att) {
    __shared__ __align__(128) unsigned Bs[2][4096];   // 2 x 16 KB
    __shared__ float snorm[S_PER_CTA];
    __shared__ float colacc[8][128];

    const int tid   = threadIdx.x;
    const int lane  = tid & 31;
    const int warp  = tid >> 5;
    const int gid   = lane >> 2;   // 0..7
    const int tig   = lane & 3;    // 0..3
    const int sgrp  = warp >> 1;   // 0..7
    const int nhalf = warp & 1;    // 0..1
    const int s_w   = blockIdx.x * S_PER_CTA + sgrp * 32;
    const int n_w   = nhalf * 64;
    const size_t SN_ = (size_t)SN;

    int  srow[4];
    bool pv[4];
#pragma unroll
    for (int j = 0; j < 4; j++) {
        srow[j] = s_w + 8 * j + gid;
        pv[j]   = (srow[j] < SN);
    }

    float acc[2][8][4];
#pragma unroll
    for (int a = 0; a < 2; a++)
#pragma unroll
        for (int b = 0; b < 8; b++)
#pragma unroll
            for (int c = 0; c < 4; c++) acc[a][b][c] = 0.0f;
    float sq[4] = {0.f, 0.f, 0.f, 0.f};

    // pointer for k-step q: attq = att + (q*16 + 2*tig)*SN; loads at
    //   +0 (k=2tig), +SN (2tig+1), +8SN (2tig+8), +9SN (2tig+9)
    const float* attq = att + (size_t)(2 * tig) * SN_;

    // prologue: stage chunk 0 (16 KB: 1024 x 16B; 512 threads x 2)
    {
#pragma unroll
        for (int i = 0; i < 2; i++) {
            int w = (tid + i * 512) * 4;
            cp_async16(&Bs[0][w], &g_B[w]);
        }
        asm volatile("cp.async.commit_group;\n");
    }

    for (int kt = 0; kt < 8; ++kt) {
        if (kt < 7) {
            const unsigned* src = g_B + (kt + 1) * 4096;
            unsigned* dst = &Bs[(kt + 1) & 1][0];
#pragma unroll
            for (int i = 0; i < 2; i++) {
                int w = (tid + i * 512) * 4;
                cp_async16(dst + w, src + w);
            }
            asm volatile("cp.async.commit_group;\n");
            asm volatile("cp.async.wait_group 1;\n");
        } else {
            asm volatile("cp.async.wait_group 0;\n");
        }
        __syncthreads();

        const uint2* bch = (const uint2*)(&Bs[kt & 1][0]);
#pragma unroll
        for (int ks = 0; ks < 4; ++ks) {
            unsigned A[2][4];
#pragma unroll
            for (int mf = 0; mf < 2; ++mf) {
                int j0 = 2 * mf, j1 = 2 * mf + 1;
                float f00, f01, f02, f03, f10, f11, f12, f13;
                if (pv[j0]) {
                    f00 = attq[srow[j0]];
                    f01 = attq[SN_ + srow[j0]];
                    f02 = attq[8 * SN_ + srow[j0]];
                    f03 = attq[9 * SN_ + srow[j0]];
                } else { f00 = f01 = f02 = f03 = 0.f; }
                if (pv[j1]) {
                    f10 = attq[srow[j1]];
                    f11 = attq[SN_ + srow[j1]];
                    f12 = attq[8 * SN_ + srow[j1]];
                    f13 = attq[9 * SN_ + srow[j1]];
                } else { f10 = f11 = f12 = f13 = 0.f; }
                sq[j0] += f00 * f00 + f01 * f01 + f02 * f02 + f03 * f03;
                sq[j1] += f10 * f10 + f11 * f11 + f12 * f12 + f13 * f13;
                A[mf][0] = pack_bf16x2(f00, f01);
                A[mf][1] = pack_bf16x2(f10, f11);
                A[mf][2] = pack_bf16x2(f02, f03);
                A[mf][3] = pack_bf16x2(f12, f13);
            }
            attq += 16 * SN_;
            const uint2* brow = bch + (ks * 128 + n_w) * 4 + tig;
#pragma unroll
            for (int nt = 0; nt < 8; ++nt) {
                uint2 b = brow[(nt * 8 + gid) * 4];
                mma_bf16(acc[0][nt], A[0], b.x, b.y);
                mma_bf16(acc[1][nt], A[1], b.x, b.y);
            }
        }
        __syncthreads();
    }

    // norm^2: quad-reduce over tig (each tig covered k%16 in {2t,2t+1,2t+8,2t+9})
#pragma unroll
    for (int j = 0; j < 4; j++) {
        sq[j] += __shfl_xor_sync(0xffffffffu, sq[j], 1);
        sq[j] += __shfl_xor_sync(0xffffffffu, sq[j], 2);
    }
    if (nhalf == 0 && tig == 0) {
#pragma unroll
        for (int j = 0; j < 4; j++)
            snorm[sgrp * 32 + 8 * j + gid] = sq[j];
    }
    __syncthreads();

    float inv[4];
#pragma unroll
    for (int j = 0; j < 4; j++)
        inv[j] = rsqrtf(snorm[sgrp * 32 + 8 * j + gid]);

    // epilogue: exp + deterministic reductions
#pragma unroll
    for (int nt = 0; nt < 8; ++nt) {
        float s0 = 0.f, s1 = 0.f;
#pragma unroll
        for (int mf = 0; mf < 2; ++mf) {
            int j0 = 2 * mf, j1 = 2 * mf + 1;
            if (pv[j0]) {
                s0 += __expf(acc[mf][nt][0] * inv[j0]);
                s1 += __expf(acc[mf][nt][1] * inv[j0]);
            }
            if (pv[j1]) {
                s0 += __expf(acc[mf][nt][2] * inv[j1]);
                s1 += __expf(acc[mf][nt][3] * inv[j1]);
            }
        }
        s0 += __shfl_down_sync(0xffffffffu, s0, 16);
        s1 += __shfl_down_sync(0xffffffffu, s1, 16);
        s0 += __shfl_down_sync(0xffffffffu, s0, 8);
        s1 += __shfl_down_sync(0xffffffffu, s1, 8);
        s0 += __shfl_down_sync(0xffffffffu, s0, 4);
        s1 += __shfl_down_sync(0xffffffffu, s1, 4);
        if (gid == 0) {
            colacc[sgrp][n_w + nt * 8 + 2 * tig]     = s0;
            colacc[sgrp][n_w + nt * 8 + 2 * tig + 1] = s1;
        }
    }
    __syncthreads();

    if (tid < 128) {
        float t = 0.f;
#pragma unroll
        for (int g = 0; g < 8; ++g) t += colacc[g][tid];
        g_Psum[blockIdx.x * 128 + tid] = t;
    }
}

// ---------------------------------------------------------------------------
// reduce: parallel per-n sum over the 586 CTA partials -> logZ
// ---------------------------------------------------------------------------
__global__ void reduce_kernel() {
    int n = blockIdx.x;    // 0..127
    int t = threadIdx.x;   // 256
    __shared__ float red[256];
    float sum = 0.f;
    for (int c = t; c < NCTA; c += 256) sum += g_Psum[c * 128 + n];
    red[t] = sum; __syncthreads();
    for (int off = 128; off > 0; off >>= 1) { if (t < off) red[t] += red[t + off]; __syncthreads(); }
    if (t == 0) g_logZ[n] = logf(red[0]);
}

__global__ void final_kernel(float* __restrict__ out) {
    int t = threadIdx.x;   // 128
    __shared__ float red[128];
    float v = (t < NB) ? (g_logZ[t] - g_pos[t]) : 0.f;
    red[t] = v; __syncthreads();
    for (int off = 64; off > 0; off >>= 1) { if (t < off) red[t] += red[t + off]; __syncthreads(); }
    if (t == 0) out[0] = red[0] / (float)NB;
}

// ---------------------------------------------------------------------------
extern "C" void kernel_launch(void* const* d_in, const int* in_sizes, int n_in,
                              void* d_out, int out_size) {
    int ia = 0, ifea = 1, ilab = 2;
    for (int i = 0; i < n_in; i++) {
        if (in_sizes[i] > 10000000) ia = i;
        else if (in_sizes[i] > 100000) ifea = i;
        else ilab = i;
    }
    const float* att   = (const float*)d_in[ia];
    const float* fea   = (const float*)d_in[ifea];
    const int*   label = (const int*)d_in[ilab];
    float* out = (float*)d_out;

    prep_kernel<<<128, 128>>>(fea);
    pos_kernel<<<NB, 128>>>(att, fea, label);
    main_kernel<<<NCTA, 512>>>(att);
    reduce_kernel<<<128, 256>>>();
    final_kernel<<<1, 128>>>(out);
}

// round 5
// speedup vs baseline: 1.2139x; 1.1438x over previous
#include <cuda_runtime.h>
#include <cuda_fp16.h>
#include <cstdint>
#include <math.h>

#define SN       150000
#define DIM      512
#define NB       100
#define NUSE     104                 // computed n columns (13 tiles of 8)
#define TALF     0.07f
#define S_PER_CTA 256
#define NCTA     ((SN + S_PER_CTA - 1) / S_PER_CTA)   // 586

// Static device scratch (no allocations allowed)
// g_B: f16x2 words, fragment-packed, padded to 128 n: word[(kstep*128 + n)*8 + c]
//   kstep = k/16 (32 steps); for even r = k%16: c = (r<8) ? r : r-7
__device__ __align__(1024) unsigned g_B[32 * 128 * 8];   // 128 KB
__device__ float g_Psum[NCTA * 128];
__device__ float g_pos[128];
__device__ float g_logZ[128];

// ---------------------------------------------------------------------------
__device__ __forceinline__ unsigned pack_f16x2(float lo, float hi) {
    unsigned r;  // first source -> high half
    asm("cvt.rn.f16x2.f32 %0, %1, %2;" : "=r"(r) : "f"(hi), "f"(lo));
    return r;
}
// m16n8k16 f16 in / f16 accum: C/D = 2 x f16x2 regs
__device__ __forceinline__ void mma_f16acc(unsigned c[2], const unsigned a[4],
                                           unsigned b0, unsigned b1) {
    asm volatile(
        "mma.sync.aligned.m16n8k16.row.col.f16.f16.f16.f16 "
        "{%0,%1},{%2,%3,%4,%5},{%6,%7},{%0,%1};\n"
        : "+r"(c[0]), "+r"(c[1])
        : "r"(a[0]), "r"(a[1]), "r"(a[2]), "r"(a[3]), "r"(b0), "r"(b1));
}
__device__ __forceinline__ void cp_async16(void* smem_dst, const void* gsrc) {
    unsigned s = (unsigned)__cvta_generic_to_shared(smem_dst);
    asm volatile("cp.async.cg.shared.global [%0], [%1], 16;\n" :: "r"(s), "l"(gsrc));
}

// ---------------------------------------------------------------------------
// prep: B'[n][k] = f16( fea[n][k] / (TAL*||fea[n]||) ), n zero-padded to 128,
// packed into g_B fragment layout. One block per n (128 blocks, 128 threads).
// ---------------------------------------------------------------------------
__global__ void prep_kernel(const float* __restrict__ fea) {
    int n = blockIdx.x;   // 0..127
    int t = threadIdx.x;  // 128
    __shared__ float red[128];
    __shared__ float row[512];
    float v[4]; float ss = 0.f;
    if (n < NB) {
#pragma unroll
        for (int i = 0; i < 4; i++) { v[i] = fea[n * DIM + t + i * 128]; ss += v[i] * v[i]; }
    } else { v[0] = v[1] = v[2] = v[3] = 0.f; }
    red[t] = ss; __syncthreads();
    for (int off = 64; off > 0; off >>= 1) { if (t < off) red[t] += red[t + off]; __syncthreads(); }
    float scale = (n < NB) ? (rsqrtf(red[0]) / TALF) : 0.f;
#pragma unroll
    for (int i = 0; i < 4; i++) row[t + i * 128] = v[i] * scale;
    __syncthreads();
#pragma unroll
    for (int i = 0; i < 2; i++) {
        int k0 = 4 * t + 2 * i;           // even, 0..510
        int kstep = k0 >> 4;
        int r = k0 & 15;
        int c = (r < 8) ? r : (r - 7);
        g_B[(kstep * 128 + n) * 8 + c] = pack_f16x2(row[k0], row[k0 + 1]);
    }
}

// ---------------------------------------------------------------------------
// pos: ex[label[n], n] exact fp32; label dtype sniffed (int64 vs int32)
// ---------------------------------------------------------------------------
__global__ void pos_kernel(const float* __restrict__ att,
                           const float* __restrict__ fea,
                           const int* __restrict__ label_raw) {
    int n = blockIdx.x, t = threadIdx.x;
    bool is64 = (label_raw[1] == 0) && (label_raw[3] == 0) &&
                (label_raw[5] == 0) && (label_raw[7] == 0);
    int lab = is64 ? (int)(((const long long*)label_raw)[n]) : label_raw[n];
    if (lab < 0) lab = 0;
    if (lab >= SN) lab = SN - 1;
    float dot = 0.f, asq = 0.f, fsq = 0.f;
    for (int d = t; d < DIM; d += 128) {
        float a = att[(size_t)d * SN + (size_t)lab];
        float f = fea[n * DIM + d];
        dot += a * f; asq += a * a; fsq += f * f;
    }
    __shared__ float r1[128], r2[128], r3[128];
    r1[t] = dot; r2[t] = asq; r3[t] = fsq; __syncthreads();
    for (int off = 64; off > 0; off >>= 1) {
        if (t < off) { r1[t] += r1[t+off]; r2[t] += r2[t+off]; r3[t] += r3[t+off]; }
        __syncthreads();
    }
    if (t == 0) g_pos[n] = r1[0] / (TALF * sqrtf(r2[0]) * sqrtf(r3[0]));
}

// ---------------------------------------------------------------------------
// main: 586 CTAs x 512 threads (16 warps). CTA tile 256 s x 104 n, K=512.
//   warp: sgrp = warp/2 (32 s-rows); nhalf=0 -> n-tiles 0..6, nhalf=1 -> 7..12.
//   f16 m16n8k16 with f16 accumulators (2x legacy HMMA rate hypothesis).
//   A gmem->fp32 regs (exact norms) -> f16x2; B from smem, double-buffered.
// ---------------------------------------------------------------------------
__global__ void __launch_bounds__(512, 1)
main_kernel(const float* __restrict__ att) {
    __shared__ __align__(128) unsigned Bs[2][4096];   // 2 x 16 KB
    __shared__ float snorm[S_PER_CTA];
    __shared__ float colacc[8][NUSE];

    const int tid   = threadIdx.x;
    const int lane  = tid & 31;
    const int warp  = tid >> 5;
    const int gid   = lane >> 2;   // 0..7
    const int tig   = lane & 3;    // 0..3
    const int sgrp  = warp >> 1;   // 0..7
    const int nhalf = warp & 1;    // 0..1
    const int s_w   = blockIdx.x * S_PER_CTA + sgrp * 32;
    const int ft    = nhalf * 7;       // first n-tile
    const int NT    = 7 - nhalf;       // tiles this warp owns (7 or 6)
    const size_t SN_ = (size_t)SN;

    int  srow[4];
    bool pv[4];
#pragma unroll
    for (int j = 0; j < 4; j++) {
        srow[j] = s_w + 8 * j + gid;
        pv[j]   = (srow[j] < SN);
    }

    unsigned acc[2][7][2];
#pragma unroll
    for (int a = 0; a < 2; a++)
#pragma unroll
        for (int b = 0; b < 7; b++) { acc[a][b][0] = 0u; acc[a][b][1] = 0u; }
    float sq[4] = {0.f, 0.f, 0.f, 0.f};

    const float* attq = att + (size_t)(2 * tig) * SN_;

    // prologue: stage chunk 0 (16 KB)
    {
#pragma unroll
        for (int i = 0; i < 2; i++) {
            int w = (tid + i * 512) * 4;
            cp_async16(&Bs[0][w], &g_B[w]);
        }
        asm volatile("cp.async.commit_group;\n");
    }

    for (int kt = 0; kt < 8; ++kt) {
        if (kt < 7) {
            const unsigned* src = g_B + (kt + 1) * 4096;
            unsigned* dst = &Bs[(kt + 1) & 1][0];
#pragma unroll
            for (int i = 0; i < 2; i++) {
                int w = (tid + i * 512) * 4;
                cp_async16(dst + w, src + w);
            }
            asm volatile("cp.async.commit_group;\n");
            asm volatile("cp.async.wait_group 1;\n");
        } else {
            asm volatile("cp.async.wait_group 0;\n");
        }
        __syncthreads();

        const uint2* bch = (const uint2*)(&Bs[kt & 1][0]);
#pragma unroll
        for (int ks = 0; ks < 4; ++ks) {
            unsigned A[2][4];
#pragma unroll
            for (int mf = 0; mf < 2; ++mf) {
                int j0 = 2 * mf, j1 = 2 * mf + 1;
                float f00, f01, f02, f03, f10, f11, f12, f13;
                if (pv[j0]) {
                    f00 = attq[srow[j0]];
                    f01 = attq[SN_ + srow[j0]];
                    f02 = attq[8 * SN_ + srow[j0]];
                    f03 = attq[9 * SN_ + srow[j0]];
                } else { f00 = f01 = f02 = f03 = 0.f; }
                if (pv[j1]) {
                    f10 = attq[srow[j1]];
                    f11 = attq[SN_ + srow[j1]];
                    f12 = attq[8 * SN_ + srow[j1]];
                    f13 = attq[9 * SN_ + srow[j1]];
                } else { f10 = f11 = f12 = f13 = 0.f; }
                sq[j0] += f00 * f00 + f01 * f01 + f02 * f02 + f03 * f03;
                sq[j1] += f10 * f10 + f11 * f11 + f12 * f12 + f13 * f13;
                A[mf][0] = pack_f16x2(f00, f01);
                A[mf][1] = pack_f16x2(f10, f11);
                A[mf][2] = pack_f16x2(f02, f03);
                A[mf][3] = pack_f16x2(f12, f13);
            }
            attq += 16 * SN_;
            const uint2* brow = bch + (ks * 128) * 4 + tig;
#pragma unroll
            for (int nt = 0; nt < 7; ++nt) {
                if (nt < NT) {
                    uint2 b = brow[((ft + nt) * 8 + gid) * 4];
                    mma_f16acc(acc[0][nt], A[0], b.x, b.y);
                    mma_f16acc(acc[1][nt], A[1], b.x, b.y);
                }
            }
        }
        __syncthreads();
    }

    // norm^2: quad-reduce over tig (each tig covered k%16 in {2t,2t+1,2t+8,2t+9})
#pragma unroll
    for (int j = 0; j < 4; j++) {
        sq[j] += __shfl_xor_sync(0xffffffffu, sq[j], 1);
        sq[j] += __shfl_xor_sync(0xffffffffu, sq[j], 2);
    }
    if (nhalf == 0 && tig == 0) {
#pragma unroll
        for (int j = 0; j < 4; j++)
            snorm[sgrp * 32 + 8 * j + gid] = sq[j];
    }
    __syncthreads();

    float inv[4];
#pragma unroll
    for (int j = 0; j < 4; j++)
        inv[j] = rsqrtf(snorm[sgrp * 32 + 8 * j + gid]);

    // epilogue: unpack f16 accum -> fp32, scale, exp, deterministic reductions
#pragma unroll
    for (int nt = 0; nt < 7; ++nt) {
        if (nt >= NT) break;
        float s0 = 0.f, s1 = 0.f;
#pragma unroll
        for (int mf = 0; mf < 2; ++mf) {
            int j0 = 2 * mf, j1 = 2 * mf + 1;
            float2 v0 = __half22float2(*reinterpret_cast<__half2*>(&acc[mf][nt][0])); // row j0
            float2 v1 = __half22float2(*reinterpret_cast<__half2*>(&acc[mf][nt][1])); // row j1
            if (pv[j0]) {
                s0 += __expf(v0.x * inv[j0]);
                s1 += __expf(v0.y * inv[j0]);
            }
            if (pv[j1]) {
                s0 += __expf(v1.x * inv[j1]);
                s1 += __expf(v1.y * inv[j1]);
            }
        }
        s0 += __shfl_down_sync(0xffffffffu, s0, 16);
        s1 += __shfl_down_sync(0xffffffffu, s1, 16);
        s0 += __shfl_down_sync(0xffffffffu, s0, 8);
        s1 += __shfl_down_sync(0xffffffffu, s1, 8);
        s0 += __shfl_down_sync(0xffffffffu, s0, 4);
        s1 += __shfl_down_sync(0xffffffffu, s1, 4);
        if (gid == 0) {
            colacc[sgrp][(ft + nt) * 8 + 2 * tig]     = s0;
            colacc[sgrp][(ft + nt) * 8 + 2 * tig + 1] = s1;
        }
    }
    __syncthreads();

    if (tid < NUSE) {
        float t = 0.f;
#pragma unroll
        for (int g = 0; g < 8; ++g) t += colacc[g][tid];
        g_Psum[blockIdx.x * 128 + tid] = t;
    }
}

// ---------------------------------------------------------------------------
// reduce: parallel per-n sum over the 586 CTA partials -> logZ
// ---------------------------------------------------------------------------
__global__ void reduce_kernel() {
    int n = blockIdx.x;    // 0..NUSE-1
    int t = threadIdx.x;   // 256
    __shared__ float red[256];
    float sum = 0.f;
    for (int c = t; c < NCTA; c += 256) sum += g_Psum[c * 128 + n];
    red[t] = sum; __syncthreads();
    for (int off = 128; off > 0; off >>= 1) { if (t < off) red[t] += red[t + off]; __syncthreads(); }
    if (t == 0) g_logZ[n] = logf(red[0]);
}

__global__ void final_kernel(float* __restrict__ out) {
    int t = threadIdx.x;   // 128
    __shared__ float red[128];
    float v = (t < NB) ? (g_logZ[t] - g_pos[t]) : 0.f;
    red[t] = v; __syncthreads();
    for (int off = 64; off > 0; off >>= 1) { if (t < off) red[t] += red[t + off]; __syncthreads(); }
    if (t == 0) out[0] = red[0] / (float)NB;
}

// ---------------------------------------------------------------------------
extern "C" void kernel_launch(void* const* d_in, const int* in_sizes, int n_in,
                              void* d_out, int out_size) {
    int ia = 0, ifea = 1, ilab = 2;
    for (int i = 0; i < n_in; i++) {
        if (in_sizes[i] > 10000000) ia = i;
        else if (in_sizes[i] > 100000) ifea = i;
        else ilab = i;
    }
    const float* att   = (const float*)d_in[ia];
    const float* fea   = (const float*)d_in[ifea];
    const int*   label = (const int*)d_in[ilab];
    float* out = (float*)d_out;

    prep_kernel<<<128, 128>>>(fea);
    pos_kernel<<<NB, 128>>>(att, fea, label);
    main_kernel<<<NCTA, 512>>>(att);
    reduce_kernel<<<NUSE, 256>>>();
    final_kernel<<<1, 128>>>(out);
}